// round 3
// baseline (speedup 1.0000x reference)
#include <cuda_runtime.h>
#include <math_constants.h>

// Problem constants (fixed by the dataset)
#define NN   20000      // nodes
#define EE   640000     // edges
#define HCC  128        // H * C
#define NH   4          // heads
#define CH   32         // channels per head
#define DOUT 64

// ---------------- device scratch (static: no allocations allowed) -----------
__device__ float g_XL[NN * HCC];
__device__ float g_XR[NN * HCC];
__device__ float g_H [NN * HCC];
__device__ int   g_cnt[NN];
__device__ int   g_cur[NN];
__device__ int   g_rowptr[NN + 1];
__device__ int   g_esrc[EE];
__device__ float g_eattr[EE];
__device__ float g_loopattr[NN];

// ---------------- CSR build ------------------------------------------------
__global__ void zero_counts_kernel() {
    int i = blockIdx.x * blockDim.x + threadIdx.x;
    if (i < NN) { g_cnt[i] = 0; g_cur[i] = 0; }
}

__global__ void hist_kernel(const int* __restrict__ ei, int E) {
    int e = blockIdx.x * blockDim.x + threadIdx.x;
    if (e < E) {
        int d = ei[E + e];
        if (d >= 0 && d < NN) atomicAdd(&g_cnt[d], 1);
    }
}

// single-block exclusive scan of g_cnt -> g_rowptr
__global__ void scan_kernel(int n) {
    __shared__ int sums[1024];
    int tid = threadIdx.x;
    int per = (n + 1023) >> 10;
    int beg = tid * per;
    int end = beg + per;
    if (beg > n) beg = n;
    if (end > n) end = n;
    int s = 0;
    for (int i = beg; i < end; ++i) s += g_cnt[i];
    sums[tid] = s;
    __syncthreads();
    for (int off = 1; off < 1024; off <<= 1) {
        int v = (tid >= off) ? sums[tid - off] : 0;
        __syncthreads();
        sums[tid] += v;
        __syncthreads();
    }
    int run = (tid == 0) ? 0 : sums[tid - 1];
    for (int i = beg; i < end; ++i) { g_rowptr[i] = run; run += g_cnt[i]; }
    if (tid == 0) g_rowptr[n] = sums[1023];
}

__global__ void scatter_kernel(const int* __restrict__ ei,
                               const float* __restrict__ eattr, int E) {
    int e = blockIdx.x * blockDim.x + threadIdx.x;
    if (e >= E) return;
    int dst = ei[E + e];
    if (dst < 0 || dst >= NN) return;
    int pos = g_rowptr[dst] + atomicAdd(&g_cur[dst], 1);
    g_esrc[pos]  = ei[e];
    g_eattr[pos] = eattr[e];
}

// per-dst mean of incoming non-self edge_attr (PyG fill_value='mean')
__global__ void loopattr_kernel() {
    int gid  = blockIdx.x * blockDim.x + threadIdx.x;
    int wid  = gid >> 5;
    int lane = gid & 31;
    if (wid >= NN) return;
    int beg = g_rowptr[wid], end = g_rowptr[wid + 1];
    float s = 0.f; int c = 0;
    for (int e = beg + lane; e < end; e += 32) {
        if (g_esrc[e] != wid) { s += g_eattr[e]; c++; }
    }
    #pragma unroll
    for (int off = 16; off; off >>= 1) {
        s += __shfl_xor_sync(0xffffffffu, s, off);
        c += __shfl_xor_sync(0xffffffffu, c, off);
    }
    if (lane == 0) g_loopattr[wid] = (c > 0) ? s / (float)c : 0.f;
}

// ---------------- SGEMM: C[M,N] = A[M,K] @ B[K,N] + bias --------------------
// 64x64 tile, BK=16, 256 threads, 4x4 per thread, float4 fragments
__global__ __launch_bounds__(256)
void sgemm_bias(const float* __restrict__ A, const float* __restrict__ B,
                const float* __restrict__ bias, float* __restrict__ C,
                int M, int N, int K) {
    __shared__ float As[16][64];   // transposed: As[k][m]
    __shared__ float Bs[16][64];   // Bs[k][n]
    int tid = threadIdx.x;
    int tx = tid & 15, ty = tid >> 4;
    int bm = blockIdx.x, bn = blockIdx.y;
    int rowBase = bm * 64;

    int aRow = tid >> 2;          // 0..63
    int aK   = (tid & 3) * 4;     // 0,4,8,12
    int bK   = tid >> 4;          // 0..15
    int bN   = (tid & 15) * 4;    // 0..60

    float acc[4][4] = {};
    for (int k0 = 0; k0 < K; k0 += 16) {
        float4 av;
        int gr = rowBase + aRow;
        if (gr < M) av = *(const float4*)&A[(long)gr * K + k0 + aK];
        else        av = make_float4(0.f, 0.f, 0.f, 0.f);
        As[aK + 0][aRow] = av.x;
        As[aK + 1][aRow] = av.y;
        As[aK + 2][aRow] = av.z;
        As[aK + 3][aRow] = av.w;
        float4 bv = *(const float4*)&B[(long)(k0 + bK) * N + bn * 64 + bN];
        *(float4*)&Bs[bK][bN] = bv;
        __syncthreads();
        #pragma unroll
        for (int kk = 0; kk < 16; ++kk) {
            float4 a4 = *(const float4*)&As[kk][ty * 4];
            float4 b4 = *(const float4*)&Bs[kk][tx * 4];
            float ar[4] = {a4.x, a4.y, a4.z, a4.w};
            float br[4] = {b4.x, b4.y, b4.z, b4.w};
            #pragma unroll
            for (int i = 0; i < 4; ++i)
                #pragma unroll
                for (int j = 0; j < 4; ++j)
                    acc[i][j] += ar[i] * br[j];
        }
        __syncthreads();
    }
    float4 bias4 = *(const float4*)&bias[bn * 64 + tx * 4];
    float bb[4] = {bias4.x, bias4.y, bias4.z, bias4.w};
    #pragma unroll
    for (int i = 0; i < 4; ++i) {
        int gr = rowBase + ty * 4 + i;
        if (gr < M) {
            float4 o;
            o.x = acc[i][0] + bb[0];
            o.y = acc[i][1] + bb[1];
            o.z = acc[i][2] + bb[2];
            o.w = acc[i][3] + bb[3];
            *(float4*)&C[(long)gr * N + bn * 64 + tx * 4] = o;
        }
    }
}

// ---------------- GATv2 edge phase: one warp per dst node ------------------
// single-pass online softmax + aggregation; one 512B gather per edge
__global__ __launch_bounds__(256)
void gat_edge_kernel(const float* __restrict__ XL, const float* __restrict__ XR,
                     const float* __restrict__ att, const float* __restrict__ We,
                     const float* __restrict__ bias, float* __restrict__ out,
                     int applyElu) {
    int gid  = blockIdx.x * blockDim.x + threadIdx.x;
    int n    = gid >> 5;
    int lane = gid & 31;
    if (n >= NN) return;

    float xr[NH], at[NH], we[NH];
    #pragma unroll
    for (int h = 0; h < NH; ++h) {
        xr[h] = XR[n * HCC + h * CH + lane];
        at[h] = att[h * CH + lane];
        we[h] = We[h * CH + lane];
    }

    float mx[NH], dn[NH], acc[NH];
    #pragma unroll
    for (int h = 0; h < NH; ++h) { mx[h] = -CUDART_INF_F; dn[h] = 0.f; acc[h] = 0.f; }

    int beg = g_rowptr[n], end = g_rowptr[n + 1];
    for (int e = beg; e < end; ++e) {
        int s = g_esrc[e];
        if (s == n) continue;                    // PyG removes existing self loops
        float ae = g_eattr[e];
        float xlv[NH], sc[NH];
        #pragma unroll
        for (int h = 0; h < NH; ++h)
            xlv[h] = __ldg(&XL[s * HCC + h * CH + lane]);
        #pragma unroll
        for (int h = 0; h < NH; ++h) {
            float m = xlv[h] + xr[h] + ae * we[h];
            m = (m > 0.f) ? m : 0.2f * m;        // leaky_relu, slope 0.2
            sc[h] = m * at[h];
        }
        #pragma unroll
        for (int off = 16; off; off >>= 1)
            #pragma unroll
            for (int h = 0; h < NH; ++h)
                sc[h] += __shfl_xor_sync(0xffffffffu, sc[h], off);
        #pragma unroll
        for (int h = 0; h < NH; ++h) {
            float sh = sc[h];
            if (sh > mx[h]) {
                float r = __expf(mx[h] - sh);    // exp(-inf)=0 first time
                dn[h] *= r; acc[h] *= r; mx[h] = sh;
            }
            float w = __expf(sh - mx[h]);
            dn[h] += w;
            acc[h] += w * xlv[h];
        }
    }

    // self loop (always added, edge_attr = loop_attr mean)
    {
        float la = g_loopattr[n];
        float xlv[NH], sc[NH];
        #pragma unroll
        for (int h = 0; h < NH; ++h)
            xlv[h] = XL[n * HCC + h * CH + lane];
        #pragma unroll
        for (int h = 0; h < NH; ++h) {
            float m = xlv[h] + xr[h] + la * we[h];
            m = (m > 0.f) ? m : 0.2f * m;
            sc[h] = m * at[h];
        }
        #pragma unroll
        for (int off = 16; off; off >>= 1)
            #pragma unroll
            for (int h = 0; h < NH; ++h)
                sc[h] += __shfl_xor_sync(0xffffffffu, sc[h], off);
        #pragma unroll
        for (int h = 0; h < NH; ++h) {
            float sh = sc[h];
            if (sh > mx[h]) {
                float r = __expf(mx[h] - sh);
                dn[h] *= r; acc[h] *= r; mx[h] = sh;
            }
            float w = __expf(sh - mx[h]);
            dn[h] += w;
            acc[h] += w * xlv[h];
        }
    }

    #pragma unroll
    for (int h = 0; h < NH; ++h) {
        float o = acc[h] / dn[h] + bias[h * CH + lane];
        if (applyElu) o = (o > 0.f) ? o : (__expf(o) - 1.f);
        out[n * HCC + h * CH + lane] = o;
    }
}

// ---------------- launch ----------------------------------------------------
extern "C" void kernel_launch(void* const* d_in, const int* in_sizes, int n_in,
                              void* d_out, int out_size) {
    const float* x     = (const float*)d_in[0];
    const int*   ei    = (const int*)d_in[1];      // int32 per harness dtype rules
    const float* eattr = (const float*)d_in[2];
    const float* Wl1 = (const float*)d_in[3];
    const float* bl1 = (const float*)d_in[4];
    const float* Wr1 = (const float*)d_in[5];
    const float* br1 = (const float*)d_in[6];
    const float* We1 = (const float*)d_in[7];
    const float* att1= (const float*)d_in[8];
    const float* b1  = (const float*)d_in[9];
    const float* Wl2 = (const float*)d_in[10];
    const float* bl2 = (const float*)d_in[11];
    const float* Wr2 = (const float*)d_in[12];
    const float* br2 = (const float*)d_in[13];
    const float* We2 = (const float*)d_in[14];
    const float* att2= (const float*)d_in[15];
    const float* b2  = (const float*)d_in[16];
    const float* Wo  = (const float*)d_in[17];
    const float* bo  = (const float*)d_in[18];
    float* out = (float*)d_out;

    int E = in_sizes[1] / 2;        // 640000
    int N = in_sizes[0] / HCC;      // 20000

    float *XL, *XR, *H;
    cudaGetSymbolAddress((void**)&XL, g_XL);
    cudaGetSymbolAddress((void**)&XR, g_XR);
    cudaGetSymbolAddress((void**)&H,  g_H);

    dim3 gemmGrid((N + 63) / 64, HCC / 64);
    dim3 gemmGridOut((N + 63) / 64, DOUT / 64);
    int edgeBlocks = (N * 32 + 255) / 256;   // one warp per node
    int eBlocks    = (E + 255) / 256;
    int nBlocks    = (N + 255) / 256;

    // CSR build (per call — no caching allowed)
    zero_counts_kernel<<<nBlocks, 256>>>();
    hist_kernel<<<eBlocks, 256>>>(ei, E);
    scan_kernel<<<1, 1024>>>(N);
    scatter_kernel<<<eBlocks, 256>>>(ei, eattr, E);
    loopattr_kernel<<<edgeBlocks, 256>>>();

    // layer 1
    sgemm_bias<<<gemmGrid, 256>>>(x, Wl1, bl1, XL, N, HCC, HCC);
    sgemm_bias<<<gemmGrid, 256>>>(x, Wr1, br1, XR, N, HCC, HCC);
    gat_edge_kernel<<<edgeBlocks, 256>>>(XL, XR, att1, We1, b1, H, 1);

    // layer 2
    sgemm_bias<<<gemmGrid, 256>>>(H, Wl2, bl2, XL, N, HCC, HCC);
    sgemm_bias<<<gemmGrid, 256>>>(H, Wr2, br2, XR, N, HCC, HCC);
    gat_edge_kernel<<<edgeBlocks, 256>>>(XL, XR, att2, We2, b2, H, 1);

    // output projection
    sgemm_bias<<<gemmGridOut, 256>>>(H, Wo, bo, out, N, DOUT, HCC);
}

// round 4
// speedup vs baseline: 1.3136x; 1.3136x over previous
#include <cuda_runtime.h>
#include <math_constants.h>

// Problem constants (fixed by the dataset)
#define NN   20000      // nodes
#define EE   640000     // edges
#define HCC  128        // H * C
#define NH   4          // heads
#define CH   32         // channels per head
#define DOUT 64

// ---------------- device scratch (static: no allocations allowed) -----------
__device__ float g_XL[NN * HCC];
__device__ float g_XR[NN * HCC];
__device__ float g_H [NN * HCC];
__device__ int   g_cnt[NN];
__device__ int   g_cur[NN];
__device__ int   g_rowptr[NN + 1];
__device__ int   g_esrc[EE];
__device__ float g_eattr[EE];
__device__ float g_loopattr[NN];

// ---------------- CSR build ------------------------------------------------
__global__ void zero_counts_kernel() {
    int i = blockIdx.x * blockDim.x + threadIdx.x;
    if (i < NN) { g_cnt[i] = 0; g_cur[i] = 0; }
}

__global__ void hist_kernel(const int* __restrict__ ei, int E) {
    int e = blockIdx.x * blockDim.x + threadIdx.x;
    if (e < E) {
        int d = ei[E + e];
        if (d >= 0 && d < NN) atomicAdd(&g_cnt[d], 1);
    }
}

// single-block exclusive scan of g_cnt -> g_rowptr
__global__ void scan_kernel(int n) {
    __shared__ int sums[1024];
    int tid = threadIdx.x;
    int per = (n + 1023) >> 10;
    int beg = tid * per;
    int end = beg + per;
    if (beg > n) beg = n;
    if (end > n) end = n;
    int s = 0;
    for (int i = beg; i < end; ++i) s += g_cnt[i];
    sums[tid] = s;
    __syncthreads();
    for (int off = 1; off < 1024; off <<= 1) {
        int v = (tid >= off) ? sums[tid - off] : 0;
        __syncthreads();
        sums[tid] += v;
        __syncthreads();
    }
    int run = (tid == 0) ? 0 : sums[tid - 1];
    for (int i = beg; i < end; ++i) { g_rowptr[i] = run; run += g_cnt[i]; }
    if (tid == 0) g_rowptr[n] = sums[1023];
}

__global__ void scatter_kernel(const int* __restrict__ ei,
                               const float* __restrict__ eattr, int E) {
    int e = blockIdx.x * blockDim.x + threadIdx.x;
    if (e >= E) return;
    int dst = ei[E + e];
    if (dst < 0 || dst >= NN) return;
    int pos = g_rowptr[dst] + atomicAdd(&g_cur[dst], 1);
    g_esrc[pos]  = ei[e];
    g_eattr[pos] = eattr[e];
}

// per-dst mean of incoming non-self edge_attr (PyG fill_value='mean')
__global__ void loopattr_kernel() {
    int gid  = blockIdx.x * blockDim.x + threadIdx.x;
    int wid  = gid >> 5;
    int lane = gid & 31;
    if (wid >= NN) return;
    int beg = g_rowptr[wid], end = g_rowptr[wid + 1];
    float s = 0.f; int c = 0;
    for (int e = beg + lane; e < end; e += 32) {
        if (g_esrc[e] != wid) { s += g_eattr[e]; c++; }
    }
    #pragma unroll
    for (int off = 16; off; off >>= 1) {
        s += __shfl_xor_sync(0xffffffffu, s, off);
        c += __shfl_xor_sync(0xffffffffu, c, off);
    }
    if (lane == 0) g_loopattr[wid] = (c > 0) ? s / (float)c : 0.f;
}

// ---------------- fused dual SGEMM: CL = A@Bl + bl, CR = A@Br + br ---------
// 64x64 tiles, BK=16, 256 threads, 4x4 per thread per output, shared A tile
__global__ __launch_bounds__(256)
void sgemm_dual_bias(const float* __restrict__ A,
                     const float* __restrict__ Bl, const float* __restrict__ Br,
                     const float* __restrict__ bl, const float* __restrict__ br,
                     float* __restrict__ CL, float* __restrict__ CR,
                     int M, int N, int K) {
    __shared__ float As [16][64];  // transposed: As[k][m]
    __shared__ float Bls[16][64];  // Bls[k][n]
    __shared__ float Brs[16][64];
    int tid = threadIdx.x;
    int tx = tid & 15, ty = tid >> 4;
    int bm = blockIdx.x, bn = blockIdx.y;
    int rowBase = bm * 64;

    int aRow = tid >> 2;          // 0..63
    int aK   = (tid & 3) * 4;     // 0,4,8,12
    int bK   = tid >> 4;          // 0..15
    int bN   = (tid & 15) * 4;    // 0..60

    float accL[4][4] = {};
    float accR[4][4] = {};
    for (int k0 = 0; k0 < K; k0 += 16) {
        float4 av;
        int gr = rowBase + aRow;
        if (gr < M) av = *(const float4*)&A[(long)gr * K + k0 + aK];
        else        av = make_float4(0.f, 0.f, 0.f, 0.f);
        As[aK + 0][aRow] = av.x;
        As[aK + 1][aRow] = av.y;
        As[aK + 2][aRow] = av.z;
        As[aK + 3][aRow] = av.w;
        long boff = (long)(k0 + bK) * N + bn * 64 + bN;
        *(float4*)&Bls[bK][bN] = *(const float4*)&Bl[boff];
        *(float4*)&Brs[bK][bN] = *(const float4*)&Br[boff];
        __syncthreads();
        #pragma unroll
        for (int kk = 0; kk < 16; ++kk) {
            float4 a4  = *(const float4*)&As [kk][ty * 4];
            float4 bl4 = *(const float4*)&Bls[kk][tx * 4];
            float4 br4 = *(const float4*)&Brs[kk][tx * 4];
            float ar[4] = {a4.x, a4.y, a4.z, a4.w};
            float blr[4] = {bl4.x, bl4.y, bl4.z, bl4.w};
            float brr[4] = {br4.x, br4.y, br4.z, br4.w};
            #pragma unroll
            for (int i = 0; i < 4; ++i)
                #pragma unroll
                for (int j = 0; j < 4; ++j) {
                    accL[i][j] += ar[i] * blr[j];
                    accR[i][j] += ar[i] * brr[j];
                }
        }
        __syncthreads();
    }
    float4 bl4 = *(const float4*)&bl[bn * 64 + tx * 4];
    float4 br4 = *(const float4*)&br[bn * 64 + tx * 4];
    float blb[4] = {bl4.x, bl4.y, bl4.z, bl4.w};
    float brb[4] = {br4.x, br4.y, br4.z, br4.w};
    #pragma unroll
    for (int i = 0; i < 4; ++i) {
        int gr = rowBase + ty * 4 + i;
        if (gr < M) {
            float4 ol, orr;
            ol.x  = accL[i][0] + blb[0]; ol.y  = accL[i][1] + blb[1];
            ol.z  = accL[i][2] + blb[2]; ol.w  = accL[i][3] + blb[3];
            orr.x = accR[i][0] + brb[0]; orr.y = accR[i][1] + brb[1];
            orr.z = accR[i][2] + brb[2]; orr.w = accR[i][3] + brb[3];
            long coff = (long)gr * N + bn * 64 + tx * 4;
            *(float4*)&CL[coff] = ol;
            *(float4*)&CR[coff] = orr;
        }
    }
}

// ---------------- single SGEMM (output projection) --------------------------
__global__ __launch_bounds__(256)
void sgemm_bias(const float* __restrict__ A, const float* __restrict__ B,
                const float* __restrict__ bias, float* __restrict__ C,
                int M, int N, int K) {
    __shared__ float As[16][64];
    __shared__ float Bs[16][64];
    int tid = threadIdx.x;
    int tx = tid & 15, ty = tid >> 4;
    int bm = blockIdx.x, bn = blockIdx.y;
    int rowBase = bm * 64;

    int aRow = tid >> 2;
    int aK   = (tid & 3) * 4;
    int bK   = tid >> 4;
    int bN   = (tid & 15) * 4;

    float acc[4][4] = {};
    for (int k0 = 0; k0 < K; k0 += 16) {
        float4 av;
        int gr = rowBase + aRow;
        if (gr < M) av = *(const float4*)&A[(long)gr * K + k0 + aK];
        else        av = make_float4(0.f, 0.f, 0.f, 0.f);
        As[aK + 0][aRow] = av.x;
        As[aK + 1][aRow] = av.y;
        As[aK + 2][aRow] = av.z;
        As[aK + 3][aRow] = av.w;
        *(float4*)&Bs[bK][bN] = *(const float4*)&B[(long)(k0 + bK) * N + bn * 64 + bN];
        __syncthreads();
        #pragma unroll
        for (int kk = 0; kk < 16; ++kk) {
            float4 a4 = *(const float4*)&As[kk][ty * 4];
            float4 b4 = *(const float4*)&Bs[kk][tx * 4];
            float ar[4] = {a4.x, a4.y, a4.z, a4.w};
            float br[4] = {b4.x, b4.y, b4.z, b4.w};
            #pragma unroll
            for (int i = 0; i < 4; ++i)
                #pragma unroll
                for (int j = 0; j < 4; ++j)
                    acc[i][j] += ar[i] * br[j];
        }
        __syncthreads();
    }
    float4 bias4 = *(const float4*)&bias[bn * 64 + tx * 4];
    float bb[4] = {bias4.x, bias4.y, bias4.z, bias4.w};
    #pragma unroll
    for (int i = 0; i < 4; ++i) {
        int gr = rowBase + ty * 4 + i;
        if (gr < M) {
            float4 o;
            o.x = acc[i][0] + bb[0];
            o.y = acc[i][1] + bb[1];
            o.z = acc[i][2] + bb[2];
            o.w = acc[i][3] + bb[3];
            *(float4*)&C[(long)gr * N + bn * 64 + tx * 4] = o;
        }
    }
}

// ---------------- GATv2 edge phase: one warp per dst node ------------------
// 8 lanes per head, 4 channels per lane (float4). One LDG.128 per lane per
// edge, 3-shuffle per-head reduction, scalar online softmax per lane.
__device__ __forceinline__ float leaky02(float m) {
    return fmaxf(m, 0.f) + 0.2f * fminf(m, 0.f);
}

__global__ __launch_bounds__(256)
void gat_edge_kernel(const float* __restrict__ XL, const float* __restrict__ XR,
                     const float* __restrict__ att, const float* __restrict__ We,
                     const float* __restrict__ bias, float* __restrict__ out,
                     int applyElu) {
    int gid  = blockIdx.x * blockDim.x + threadIdx.x;
    int n    = gid >> 5;
    int lane = gid & 31;
    if (n >= NN) return;

    int base = (lane >> 3) * CH + (lane & 7) * 4;   // head*32 + chan4
    float4 xr4 = *(const float4*)&XR[n * HCC + base];
    float4 at4 = *(const float4*)&att[base];
    float4 we4 = *(const float4*)&We[base];

    float mx = -CUDART_INF_F, dn = 0.f;
    float4 acc = make_float4(0.f, 0.f, 0.f, 0.f);

    int beg = g_rowptr[n], end = g_rowptr[n + 1];
    for (int e = beg; e < end; ++e) {
        int s = g_esrc[e];
        if (s == n) continue;                       // PyG removes existing self loops
        float ae = g_eattr[e];
        float4 xl4 = *(const float4*)&XL[s * HCC + base];
        float p = leaky02(fmaf(ae, we4.x, xl4.x + xr4.x)) * at4.x
                + leaky02(fmaf(ae, we4.y, xl4.y + xr4.y)) * at4.y
                + leaky02(fmaf(ae, we4.z, xl4.z + xr4.z)) * at4.z
                + leaky02(fmaf(ae, we4.w, xl4.w + xr4.w)) * at4.w;
        p += __shfl_xor_sync(0xffffffffu, p, 4);
        p += __shfl_xor_sync(0xffffffffu, p, 2);
        p += __shfl_xor_sync(0xffffffffu, p, 1);
        if (p > mx) {
            float r = __expf(mx - p);               // exp(-inf)=0 first time
            dn *= r;
            acc.x *= r; acc.y *= r; acc.z *= r; acc.w *= r;
            mx = p;
        }
        float w = __expf(p - mx);
        dn += w;
        acc.x = fmaf(w, xl4.x, acc.x);
        acc.y = fmaf(w, xl4.y, acc.y);
        acc.z = fmaf(w, xl4.z, acc.z);
        acc.w = fmaf(w, xl4.w, acc.w);
    }

    // self loop (always added, edge_attr = mean of incoming non-self attrs)
    {
        float la = g_loopattr[n];
        float4 xl4 = *(const float4*)&XL[n * HCC + base];
        float p = leaky02(fmaf(la, we4.x, xl4.x + xr4.x)) * at4.x
                + leaky02(fmaf(la, we4.y, xl4.y + xr4.y)) * at4.y
                + leaky02(fmaf(la, we4.z, xl4.z + xr4.z)) * at4.z
                + leaky02(fmaf(la, we4.w, xl4.w + xr4.w)) * at4.w;
        p += __shfl_xor_sync(0xffffffffu, p, 4);
        p += __shfl_xor_sync(0xffffffffu, p, 2);
        p += __shfl_xor_sync(0xffffffffu, p, 1);
        if (p > mx) {
            float r = __expf(mx - p);
            dn *= r;
            acc.x *= r; acc.y *= r; acc.z *= r; acc.w *= r;
            mx = p;
        }
        float w = __expf(p - mx);
        dn += w;
        acc.x = fmaf(w, xl4.x, acc.x);
        acc.y = fmaf(w, xl4.y, acc.y);
        acc.z = fmaf(w, xl4.z, acc.z);
        acc.w = fmaf(w, xl4.w, acc.w);
    }

    float4 b4 = *(const float4*)&bias[base];
    float inv = 1.f / dn;
    float4 o;
    o.x = fmaf(acc.x, inv, b4.x);
    o.y = fmaf(acc.y, inv, b4.y);
    o.z = fmaf(acc.z, inv, b4.z);
    o.w = fmaf(acc.w, inv, b4.w);
    if (applyElu) {
        o.x = (o.x > 0.f) ? o.x : (__expf(o.x) - 1.f);
        o.y = (o.y > 0.f) ? o.y : (__expf(o.y) - 1.f);
        o.z = (o.z > 0.f) ? o.z : (__expf(o.z) - 1.f);
        o.w = (o.w > 0.f) ? o.w : (__expf(o.w) - 1.f);
    }
    *(float4*)&out[n * HCC + base] = o;
}

// ---------------- launch ----------------------------------------------------
extern "C" void kernel_launch(void* const* d_in, const int* in_sizes, int n_in,
                              void* d_out, int out_size) {
    const float* x     = (const float*)d_in[0];
    const int*   ei    = (const int*)d_in[1];
    const float* eattr = (const float*)d_in[2];
    const float* Wl1 = (const float*)d_in[3];
    const float* bl1 = (const float*)d_in[4];
    const float* Wr1 = (const float*)d_in[5];
    const float* br1 = (const float*)d_in[6];
    const float* We1 = (const float*)d_in[7];
    const float* att1= (const float*)d_in[8];
    const float* b1  = (const float*)d_in[9];
    const float* Wl2 = (const float*)d_in[10];
    const float* bl2 = (const float*)d_in[11];
    const float* Wr2 = (const float*)d_in[12];
    const float* br2 = (const float*)d_in[13];
    const float* We2 = (const float*)d_in[14];
    const float* att2= (const float*)d_in[15];
    const float* b2  = (const float*)d_in[16];
    const float* Wo  = (const float*)d_in[17];
    const float* bo  = (const float*)d_in[18];
    float* out = (float*)d_out;

    int E = in_sizes[1] / 2;        // 640000
    int N = in_sizes[0] / HCC;      // 20000

    float *XL, *XR, *H;
    cudaGetSymbolAddress((void**)&XL, g_XL);
    cudaGetSymbolAddress((void**)&XR, g_XR);
    cudaGetSymbolAddress((void**)&H,  g_H);

    dim3 gemmGrid((N + 63) / 64, HCC / 64);
    dim3 gemmGridOut((N + 63) / 64, DOUT / 64);
    int edgeBlocks = (N * 32 + 255) / 256;   // one warp per node
    int eBlocks    = (E + 255) / 256;
    int nBlocks    = (N + 255) / 256;

    // CSR build (per call — no caching allowed)
    zero_counts_kernel<<<nBlocks, 256>>>();
    hist_kernel<<<eBlocks, 256>>>(ei, E);
    scan_kernel<<<1, 1024>>>(N);
    scatter_kernel<<<eBlocks, 256>>>(ei, eattr, E);
    loopattr_kernel<<<edgeBlocks, 256>>>();

    // layer 1
    sgemm_dual_bias<<<gemmGrid, 256>>>(x, Wl1, Wr1, bl1, br1, XL, XR, N, HCC, HCC);
    gat_edge_kernel<<<edgeBlocks, 256>>>(XL, XR, att1, We1, b1, H, 1);

    // layer 2
    sgemm_dual_bias<<<gemmGrid, 256>>>(H, Wl2, Wr2, bl2, br2, XL, XR, N, HCC, HCC);
    gat_edge_kernel<<<edgeBlocks, 256>>>(XL, XR, att2, We2, b2, H, 1);

    // output projection
    sgemm_bias<<<gemmGridOut, 256>>>(H, Wo, bo, out, N, DOUT, HCC);
}

// round 5
// speedup vs baseline: 1.4475x; 1.1020x over previous
#include <cuda_runtime.h>
#include <math_constants.h>

// Problem constants (fixed by the dataset)
#define NN   20000      // nodes
#define EE   640000     // edges
#define HCC  128        // H * C
#define NH   4          // heads
#define CH   32         // channels per head
#define DOUT 64

// ---------------- device scratch (static: no allocations allowed) -----------
__device__ float g_XL[NN * HCC];
__device__ float g_XR[NN * HCC];
__device__ float g_H [NN * HCC];
__device__ int   g_cnt[NN];
__device__ int   g_cur[NN];
__device__ float g_asum[NN];     // sum of non-self incoming edge_attr
__device__ int   g_ascnt[NN];    // count of non-self incoming edges
__device__ int   g_rowptr[NN + 1];
__device__ int2  g_ecsr[EE];     // packed (src, edge_attr bits), CSR order by dst

// ---------------- CSR build ------------------------------------------------
__global__ void zero_counts_kernel() {
    int i = blockIdx.x * blockDim.x + threadIdx.x;
    if (i < NN) { g_cnt[i] = 0; g_cur[i] = 0; g_asum[i] = 0.f; g_ascnt[i] = 0; }
}

// histogram + per-dst non-self edge_attr sum/count (for fill_value='mean')
__global__ void hist_kernel(const int* __restrict__ ei,
                            const float* __restrict__ eattr, int E) {
    int e = blockIdx.x * blockDim.x + threadIdx.x;
    if (e >= E) return;
    int s = ei[e];
    int d = ei[E + e];
    if (d < 0 || d >= NN) return;
    atomicAdd(&g_cnt[d], 1);
    if (s != d) {
        atomicAdd(&g_asum[d], eattr[e]);
        atomicAdd(&g_ascnt[d], 1);
    }
}

// single-block exclusive scan of g_cnt -> g_rowptr
__global__ void scan_kernel(int n) {
    __shared__ int sums[1024];
    int tid = threadIdx.x;
    int per = (n + 1023) >> 10;
    int beg = tid * per;
    int end = beg + per;
    if (beg > n) beg = n;
    if (end > n) end = n;
    int s = 0;
    for (int i = beg; i < end; ++i) s += g_cnt[i];
    sums[tid] = s;
    __syncthreads();
    for (int off = 1; off < 1024; off <<= 1) {
        int v = (tid >= off) ? sums[tid - off] : 0;
        __syncthreads();
        sums[tid] += v;
        __syncthreads();
    }
    int run = (tid == 0) ? 0 : sums[tid - 1];
    for (int i = beg; i < end; ++i) { g_rowptr[i] = run; run += g_cnt[i]; }
    if (tid == 0) g_rowptr[n] = sums[1023];
}

__global__ void scatter_kernel(const int* __restrict__ ei,
                               const float* __restrict__ eattr, int E) {
    int e = blockIdx.x * blockDim.x + threadIdx.x;
    if (e >= E) return;
    int dst = ei[E + e];
    if (dst < 0 || dst >= NN) return;
    int pos = g_rowptr[dst] + atomicAdd(&g_cur[dst], 1);
    g_ecsr[pos] = make_int2(ei[e], __float_as_int(eattr[e]));
}

// ---------------- fused dual SGEMM: CL = A@Bl + bl, CR = A@Br + br ---------
// 64x64 tiles, BK=16, 256 threads, 4x4 per thread per output, shared A tile
__global__ __launch_bounds__(256)
void sgemm_dual_bias(const float* __restrict__ A,
                     const float* __restrict__ Bl, const float* __restrict__ Br,
                     const float* __restrict__ bl, const float* __restrict__ br,
                     float* __restrict__ CL, float* __restrict__ CR,
                     int M, int N, int K) {
    __shared__ float As [16][64];  // transposed: As[k][m]
    __shared__ float Bls[16][64];  // Bls[k][n]
    __shared__ float Brs[16][64];
    int tid = threadIdx.x;
    int tx = tid & 15, ty = tid >> 4;
    int bm = blockIdx.x, bn = blockIdx.y;
    int rowBase = bm * 64;

    int aRow = tid >> 2;          // 0..63
    int aK   = (tid & 3) * 4;     // 0,4,8,12
    int bK   = tid >> 4;          // 0..15
    int bN   = (tid & 15) * 4;    // 0..60

    float accL[4][4] = {};
    float accR[4][4] = {};
    for (int k0 = 0; k0 < K; k0 += 16) {
        float4 av;
        int gr = rowBase + aRow;
        if (gr < M) av = *(const float4*)&A[(long)gr * K + k0 + aK];
        else        av = make_float4(0.f, 0.f, 0.f, 0.f);
        As[aK + 0][aRow] = av.x;
        As[aK + 1][aRow] = av.y;
        As[aK + 2][aRow] = av.z;
        As[aK + 3][aRow] = av.w;
        long boff = (long)(k0 + bK) * N + bn * 64 + bN;
        *(float4*)&Bls[bK][bN] = *(const float4*)&Bl[boff];
        *(float4*)&Brs[bK][bN] = *(const float4*)&Br[boff];
        __syncthreads();
        #pragma unroll
        for (int kk = 0; kk < 16; ++kk) {
            float4 a4  = *(const float4*)&As [kk][ty * 4];
            float4 bl4 = *(const float4*)&Bls[kk][tx * 4];
            float4 br4 = *(const float4*)&Brs[kk][tx * 4];
            float ar[4] = {a4.x, a4.y, a4.z, a4.w};
            float blr[4] = {bl4.x, bl4.y, bl4.z, bl4.w};
            float brr[4] = {br4.x, br4.y, br4.z, br4.w};
            #pragma unroll
            for (int i = 0; i < 4; ++i)
                #pragma unroll
                for (int j = 0; j < 4; ++j) {
                    accL[i][j] += ar[i] * blr[j];
                    accR[i][j] += ar[i] * brr[j];
                }
        }
        __syncthreads();
    }
    float4 bl4 = *(const float4*)&bl[bn * 64 + tx * 4];
    float4 br4 = *(const float4*)&br[bn * 64 + tx * 4];
    float blb[4] = {bl4.x, bl4.y, bl4.z, bl4.w};
    float brb[4] = {br4.x, br4.y, br4.z, br4.w};
    #pragma unroll
    for (int i = 0; i < 4; ++i) {
        int gr = rowBase + ty * 4 + i;
        if (gr < M) {
            float4 ol, orr;
            ol.x  = accL[i][0] + blb[0]; ol.y  = accL[i][1] + blb[1];
            ol.z  = accL[i][2] + blb[2]; ol.w  = accL[i][3] + blb[3];
            orr.x = accR[i][0] + brb[0]; orr.y = accR[i][1] + brb[1];
            orr.z = accR[i][2] + brb[2]; orr.w = accR[i][3] + brb[3];
            long coff = (long)gr * N + bn * 64 + tx * 4;
            *(float4*)&CL[coff] = ol;
            *(float4*)&CR[coff] = orr;
        }
    }
}

// ---------------- single SGEMM (output projection) --------------------------
__global__ __launch_bounds__(256)
void sgemm_bias(const float* __restrict__ A, const float* __restrict__ B,
                const float* __restrict__ bias, float* __restrict__ C,
                int M, int N, int K) {
    __shared__ float As[16][64];
    __shared__ float Bs[16][64];
    int tid = threadIdx.x;
    int tx = tid & 15, ty = tid >> 4;
    int bm = blockIdx.x, bn = blockIdx.y;
    int rowBase = bm * 64;

    int aRow = tid >> 2;
    int aK   = (tid & 3) * 4;
    int bK   = tid >> 4;
    int bN   = (tid & 15) * 4;

    float acc[4][4] = {};
    for (int k0 = 0; k0 < K; k0 += 16) {
        float4 av;
        int gr = rowBase + aRow;
        if (gr < M) av = *(const float4*)&A[(long)gr * K + k0 + aK];
        else        av = make_float4(0.f, 0.f, 0.f, 0.f);
        As[aK + 0][aRow] = av.x;
        As[aK + 1][aRow] = av.y;
        As[aK + 2][aRow] = av.z;
        As[aK + 3][aRow] = av.w;
        *(float4*)&Bs[bK][bN] = *(const float4*)&B[(long)(k0 + bK) * N + bn * 64 + bN];
        __syncthreads();
        #pragma unroll
        for (int kk = 0; kk < 16; ++kk) {
            float4 a4 = *(const float4*)&As[kk][ty * 4];
            float4 b4 = *(const float4*)&Bs[kk][tx * 4];
            float ar[4] = {a4.x, a4.y, a4.z, a4.w};
            float br[4] = {b4.x, b4.y, b4.z, b4.w};
            #pragma unroll
            for (int i = 0; i < 4; ++i)
                #pragma unroll
                for (int j = 0; j < 4; ++j)
                    acc[i][j] += ar[i] * br[j];
        }
        __syncthreads();
    }
    float4 bias4 = *(const float4*)&bias[bn * 64 + tx * 4];
    float bb[4] = {bias4.x, bias4.y, bias4.z, bias4.w};
    #pragma unroll
    for (int i = 0; i < 4; ++i) {
        int gr = rowBase + ty * 4 + i;
        if (gr < M) {
            float4 o;
            o.x = acc[i][0] + bb[0];
            o.y = acc[i][1] + bb[1];
            o.z = acc[i][2] + bb[2];
            o.w = acc[i][3] + bb[3];
            *(float4*)&C[(long)gr * N + bn * 64 + tx * 4] = o;
        }
    }
}

// ---------------- GATv2 edge phase: one warp per dst node ------------------
// 8 lanes per head, 4 channels per lane (float4). One LDG.128 per lane per
// edge, 3-shuffle per-head reduction, scalar online softmax per lane.
// Software-pipelined: next edge's (src,attr) + xl row loaded while current
// edge's reduction/exp chain executes (MLP=2).
__device__ __forceinline__ float leaky02(float m) {
    return fmaxf(m, 0.f) + 0.2f * fminf(m, 0.f);
}

__global__ __launch_bounds__(256)
void gat_edge_kernel(const float* __restrict__ XL, const float* __restrict__ XR,
                     const float* __restrict__ att, const float* __restrict__ We,
                     const float* __restrict__ bias, float* __restrict__ out,
                     int applyElu) {
    int gid  = blockIdx.x * blockDim.x + threadIdx.x;
    int n    = gid >> 5;
    int lane = gid & 31;
    if (n >= NN) return;

    int base = (lane >> 3) * CH + (lane & 7) * 4;   // head*32 + chan4
    float4 xr4 = *(const float4*)&XR[n * HCC + base];
    float4 at4 = *(const float4*)&att[base];
    float4 we4 = *(const float4*)&We[base];

    float mx = -CUDART_INF_F, dn = 0.f;
    float4 acc = make_float4(0.f, 0.f, 0.f, 0.f);

    int beg = g_rowptr[n], end = g_rowptr[n + 1];

    // pipelined prologue
    int2   edN = make_int2(0, 0);
    float4 xlN = make_float4(0.f, 0.f, 0.f, 0.f);
    if (beg < end) {
        edN = g_ecsr[beg];
        xlN = *(const float4*)&XL[(long)edN.x * HCC + base];
    }

    for (int e = beg; e < end; ++e) {
        int2   ed  = edN;
        float4 xl4 = xlN;
        if (e + 1 < end) {
            edN = g_ecsr[e + 1];
            xlN = *(const float4*)&XL[(long)edN.x * HCC + base];
        }
        if (ed.x == n) continue;                    // PyG removes existing self loops
        float ae = __int_as_float(ed.y);
        float p = leaky02(fmaf(ae, we4.x, xl4.x + xr4.x)) * at4.x
                + leaky02(fmaf(ae, we4.y, xl4.y + xr4.y)) * at4.y
                + leaky02(fmaf(ae, we4.z, xl4.z + xr4.z)) * at4.z
                + leaky02(fmaf(ae, we4.w, xl4.w + xr4.w)) * at4.w;
        p += __shfl_xor_sync(0xffffffffu, p, 4);
        p += __shfl_xor_sync(0xffffffffu, p, 2);
        p += __shfl_xor_sync(0xffffffffu, p, 1);
        if (p > mx) {
            float r = __expf(mx - p);               // exp(-inf)=0 first time
            dn *= r;
            acc.x *= r; acc.y *= r; acc.z *= r; acc.w *= r;
            mx = p;
        }
        float w = __expf(p - mx);
        dn += w;
        acc.x = fmaf(w, xl4.x, acc.x);
        acc.y = fmaf(w, xl4.y, acc.y);
        acc.z = fmaf(w, xl4.z, acc.z);
        acc.w = fmaf(w, xl4.w, acc.w);
    }

    // self loop (always added, edge_attr = mean of incoming non-self attrs)
    {
        int   c  = g_ascnt[n];
        float la = (c > 0) ? g_asum[n] / (float)c : 0.f;
        float4 xl4 = *(const float4*)&XL[n * HCC + base];
        float p = leaky02(fmaf(la, we4.x, xl4.x + xr4.x)) * at4.x
                + leaky02(fmaf(la, we4.y, xl4.y + xr4.y)) * at4.y
                + leaky02(fmaf(la, we4.z, xl4.z + xr4.z)) * at4.z
                + leaky02(fmaf(la, we4.w, xl4.w + xr4.w)) * at4.w;
        p += __shfl_xor_sync(0xffffffffu, p, 4);
        p += __shfl_xor_sync(0xffffffffu, p, 2);
        p += __shfl_xor_sync(0xffffffffu, p, 1);
        if (p > mx) {
            float r = __expf(mx - p);
            dn *= r;
            acc.x *= r; acc.y *= r; acc.z *= r; acc.w *= r;
            mx = p;
        }
        float w = __expf(p - mx);
        dn += w;
        acc.x = fmaf(w, xl4.x, acc.x);
        acc.y = fmaf(w, xl4.y, acc.y);
        acc.z = fmaf(w, xl4.z, acc.z);
        acc.w = fmaf(w, xl4.w, acc.w);
    }

    float4 b4 = *(const float4*)&bias[base];
    float inv = 1.f / dn;
    float4 o;
    o.x = fmaf(acc.x, inv, b4.x);
    o.y = fmaf(acc.y, inv, b4.y);
    o.z = fmaf(acc.z, inv, b4.z);
    o.w = fmaf(acc.w, inv, b4.w);
    if (applyElu) {
        o.x = (o.x > 0.f) ? o.x : (__expf(o.x) - 1.f);
        o.y = (o.y > 0.f) ? o.y : (__expf(o.y) - 1.f);
        o.z = (o.z > 0.f) ? o.z : (__expf(o.z) - 1.f);
        o.w = (o.w > 0.f) ? o.w : (__expf(o.w) - 1.f);
    }
    *(float4*)&out[n * HCC + base] = o;
}

// ---------------- launch ----------------------------------------------------
extern "C" void kernel_launch(void* const* d_in, const int* in_sizes, int n_in,
                              void* d_out, int out_size) {
    const float* x     = (const float*)d_in[0];
    const int*   ei    = (const int*)d_in[1];
    const float* eattr = (const float*)d_in[2];
    const float* Wl1 = (const float*)d_in[3];
    const float* bl1 = (const float*)d_in[4];
    const float* Wr1 = (const float*)d_in[5];
    const float* br1 = (const float*)d_in[6];
    const float* We1 = (const float*)d_in[7];
    const float* att1= (const float*)d_in[8];
    const float* b1  = (const float*)d_in[9];
    const float* Wl2 = (const float*)d_in[10];
    const float* bl2 = (const float*)d_in[11];
    const float* Wr2 = (const float*)d_in[12];
    const float* br2 = (const float*)d_in[13];
    const float* We2 = (const float*)d_in[14];
    const float* att2= (const float*)d_in[15];
    const float* b2  = (const float*)d_in[16];
    const float* Wo  = (const float*)d_in[17];
    const float* bo  = (const float*)d_in[18];
    float* out = (float*)d_out;

    int E = in_sizes[1] / 2;        // 640000
    int N = in_sizes[0] / HCC;      // 20000

    float *XL, *XR, *H;
    cudaGetSymbolAddress((void**)&XL, g_XL);
    cudaGetSymbolAddress((void**)&XR, g_XR);
    cudaGetSymbolAddress((void**)&H,  g_H);

    // secondary stream + events for CSR || GEMM1 overlap (host objects,
    // created once on the uncaptured correctness call, reused thereafter)
    static cudaStream_t s1 = nullptr;
    static cudaEvent_t evFork = nullptr, evJoin = nullptr;
    if (s1 == nullptr) {
        cudaStreamCreateWithFlags(&s1, cudaStreamNonBlocking);
        cudaEventCreateWithFlags(&evFork, cudaEventDisableTiming);
        cudaEventCreateWithFlags(&evJoin, cudaEventDisableTiming);
    }

    dim3 gemmGrid((N + 63) / 64, HCC / 64);
    dim3 gemmGridOut((N + 63) / 64, DOUT / 64);
    int edgeBlocks = (N * 32 + 255) / 256;   // one warp per node
    int eBlocks    = (E + 255) / 256;
    int nBlocks    = (N + 255) / 256;

    // ---- fork: CSR build on s1, layer-1 GEMM on main stream, join before edge
    cudaEventRecord(evFork, 0);
    cudaStreamWaitEvent(s1, evFork, 0);

    zero_counts_kernel<<<nBlocks, 256, 0, s1>>>();
    hist_kernel<<<eBlocks, 256, 0, s1>>>(ei, eattr, E);
    scan_kernel<<<1, 1024, 0, s1>>>(N);
    scatter_kernel<<<eBlocks, 256, 0, s1>>>(ei, eattr, E);
    cudaEventRecord(evJoin, s1);

    sgemm_dual_bias<<<gemmGrid, 256>>>(x, Wl1, Wr1, bl1, br1, XL, XR, N, HCC, HCC);

    cudaStreamWaitEvent(0, evJoin, 0);

    // layer 1 edge phase
    gat_edge_kernel<<<edgeBlocks, 256>>>(XL, XR, att1, We1, b1, H, 1);

    // layer 2
    sgemm_dual_bias<<<gemmGrid, 256>>>(H, Wl2, Wr2, bl2, br2, XL, XR, N, HCC, HCC);
    gat_edge_kernel<<<edgeBlocks, 256>>>(XL, XR, att2, We2, b2, H, 1);

    // output projection
    sgemm_bias<<<gemmGridOut, 256>>>(H, Wo, bo, out, N, DOUT, HCC);
}